// round 3
// baseline (speedup 1.0000x reference)
#include <cuda_runtime.h>
#include <math.h>

#define EMBED   768
#define NHEADS  12
#define HDIM    64
#define BATCH   16
#define SEQ     1024
#define MTOT    (BATCH*SEQ)      // 16384
#define BHEADS  (BATCH*NHEADS)   // 192
#define ATT_SCALE 0.125f         // 64^-0.5

// Scratch (allocation-free rule: __device__ globals)
__device__ float g_Q[BHEADS*SEQ*HDIM];   // [bh][n][d]
__device__ float g_K[BHEADS*SEQ*HDIM];
__device__ float g_V[BHEADS*SEQ*HDIM];
__device__ float g_A[BHEADS*SEQ*HDIM];   // attention output, [bh][n][d]

// ---------------------------------------------------------------------------
// Kernel 1: fused QKV projection.  C[m][c] = sum_k x[m][k]*W[c][k] + b[c]
// written scattered into [b][h][n][d] layout.  blockIdx.z selects Q/K/V.
// Tile 128x128x16, 256 threads, 8x8 per-thread microkernel.
// ---------------------------------------------------------------------------
__global__ __launch_bounds__(256) void qkv_gemm(
    const float* __restrict__ x,
    const float* __restrict__ Wq, const float* __restrict__ bq,
    const float* __restrict__ Wk, const float* __restrict__ bk,
    const float* __restrict__ Wv, const float* __restrict__ bv)
{
    const int p = blockIdx.z;
    const float* __restrict__ W    = (p==0) ? Wq : (p==1 ? Wk : Wv);
    const float* __restrict__ bias = (p==0) ? bq : (p==1 ? bk : bv);
    float* __restrict__ outp       = (p==0) ? g_Q : (p==1 ? g_K : g_V);

    __shared__ float As[16][128];
    __shared__ float Bs[16][128];

    const int tid = threadIdx.x;
    const int tx = tid & 15, ty = tid >> 4;
    const int m0 = blockIdx.y * 128;
    const int n0 = blockIdx.x * 128;
    const int lr = tid >> 2;          // 0..63
    const int lk = (tid & 3) << 2;    // 0,4,8,12

    float acc[8][8];
    #pragma unroll
    for (int i = 0; i < 8; i++)
        #pragma unroll
        for (int j = 0; j < 8; j++) acc[i][j] = 0.f;

    for (int k0 = 0; k0 < EMBED; k0 += 16) {
        float4 a0 = *(const float4*)&x[(size_t)(m0+lr   )*EMBED + k0 + lk];
        float4 a1 = *(const float4*)&x[(size_t)(m0+lr+64)*EMBED + k0 + lk];
        float4 b0 = *(const float4*)&W[(size_t)(n0+lr   )*EMBED + k0 + lk];
        float4 b1 = *(const float4*)&W[(size_t)(n0+lr+64)*EMBED + k0 + lk];
        __syncthreads();
        As[lk+0][lr]    = a0.x; As[lk+1][lr]    = a0.y; As[lk+2][lr]    = a0.z; As[lk+3][lr]    = a0.w;
        As[lk+0][lr+64] = a1.x; As[lk+1][lr+64] = a1.y; As[lk+2][lr+64] = a1.z; As[lk+3][lr+64] = a1.w;
        Bs[lk+0][lr]    = b0.x; Bs[lk+1][lr]    = b0.y; Bs[lk+2][lr]    = b0.z; Bs[lk+3][lr]    = b0.w;
        Bs[lk+0][lr+64] = b1.x; Bs[lk+1][lr+64] = b1.y; Bs[lk+2][lr+64] = b1.z; Bs[lk+3][lr+64] = b1.w;
        __syncthreads();
        #pragma unroll
        for (int kk = 0; kk < 16; kk++) {
            float ra[8], rb[8];
            *(float4*)&ra[0] = *(const float4*)&As[kk][ty*8];
            *(float4*)&ra[4] = *(const float4*)&As[kk][ty*8+4];
            *(float4*)&rb[0] = *(const float4*)&Bs[kk][tx*8];
            *(float4*)&rb[4] = *(const float4*)&Bs[kk][tx*8+4];
            #pragma unroll
            for (int i = 0; i < 8; i++)
                #pragma unroll
                for (int j = 0; j < 8; j++)
                    acc[i][j] = fmaf(ra[i], rb[j], acc[i][j]);
        }
    }

    // Epilogue: scatter into [b][h][n][d]
    #pragma unroll
    for (int i = 0; i < 8; i++) {
        const int m  = m0 + ty*8 + i;
        const int b_ = m >> 10;
        const int nn = m & 1023;
        #pragma unroll
        for (int j = 0; j < 8; j++) {
            const int c = n0 + tx*8 + j;
            const int h = c >> 6;
            const int d = c & 63;
            outp[(((size_t)b_*NHEADS + h)*SEQ + nn)*HDIM + d] = acc[i][j] + bias[c];
        }
    }
}

// ---------------------------------------------------------------------------
// Kernel 2: flash attention per (b,h).  64-query blocks, 64-key tiles, d=64.
// grid (SEQ/64, BHEADS), 256 threads.  Dynamic smem 66304 B.
// ---------------------------------------------------------------------------
__global__ __launch_bounds__(256) void attn_kernel()
{
    extern __shared__ float sm[];
    float* Qst = sm;              // [d][r]   4096  (pre-scaled by ATT_SCALE)
    float* Kst = Qst + 4096;      // [d][c]   4096
    float* Vs  = Kst + 4096;      // [c][d]   4096
    float* Ssm = Vs  + 4096;      // [r][c]   4096
    float* m_s     = Ssm + 4096;  // [64]
    float* l_s     = m_s + 64;    // [64]
    float* alpha_s = l_s + 64;    // [64]

    const int tid  = threadIdx.x;
    const int tx   = tid & 15, ty = tid >> 4;
    const int lane = tid & 31, warp = tid >> 5;
    const int bh   = blockIdx.y;
    const int q0   = blockIdx.x * 64;

    const float* __restrict__ Qg = g_Q + ((size_t)bh*SEQ + q0)*HDIM;
    const float* __restrict__ Kg = g_K + (size_t)bh*SEQ*HDIM;
    const float* __restrict__ Vg = g_V + (size_t)bh*SEQ*HDIM;
    float* __restrict__ Og = g_A + ((size_t)bh*SEQ + q0)*HDIM;

    // Load + transpose + scale Q tile
    #pragma unroll
    for (int it = 0; it < 4; it++) {
        int idx = tid + it*256;          // 1024 float4 slots
        int r = idx >> 4, dv = (idx & 15) << 2;
        float4 q = *(const float4*)&Qg[r*HDIM + dv];
        Qst[(dv+0)*64 + r] = q.x * ATT_SCALE;
        Qst[(dv+1)*64 + r] = q.y * ATT_SCALE;
        Qst[(dv+2)*64 + r] = q.z * ATT_SCALE;
        Qst[(dv+3)*64 + r] = q.w * ATT_SCALE;
    }
    if (tid < 64) { m_s[tid] = -1e30f; l_s[tid] = 0.f; }

    float o[4][4];
    #pragma unroll
    for (int i = 0; i < 4; i++)
        #pragma unroll
        for (int j = 0; j < 4; j++) o[i][j] = 0.f;

    for (int t = 0; t < SEQ/64; t++) {
        const int c0 = t * 64;
        __syncthreads();   // previous PV / softmax done before overwriting tiles
        #pragma unroll
        for (int it = 0; it < 4; it++) {
            int idx = tid + it*256;
            int r = idx >> 4, dv = (idx & 15) << 2;
            float4 k = *(const float4*)&Kg[(c0 + r)*HDIM + dv];
            Kst[(dv+0)*64 + r] = k.x;
            Kst[(dv+1)*64 + r] = k.y;
            Kst[(dv+2)*64 + r] = k.z;
            Kst[(dv+3)*64 + r] = k.w;
            float4 v = *(const float4*)&Vg[(c0 + r)*HDIM + dv];
            *(float4*)&Vs[r*64 + dv] = v;
        }
        __syncthreads();

        // S = (Q*scale) @ K^T   : thread computes 4x4 (rows ty*4+i, cols tx*4+j)
        float s[4][4];
        #pragma unroll
        for (int i = 0; i < 4; i++)
            #pragma unroll
            for (int j = 0; j < 4; j++) s[i][j] = 0.f;
        #pragma unroll 8
        for (int d = 0; d < 64; d++) {
            float qa[4], kb[4];
            *(float4*)&qa[0] = *(const float4*)&Qst[d*64 + ty*4];
            *(float4*)&kb[0] = *(const float4*)&Kst[d*64 + tx*4];
            #pragma unroll
            for (int i = 0; i < 4; i++)
                #pragma unroll
                for (int j = 0; j < 4; j++)
                    s[i][j] = fmaf(qa[i], kb[j], s[i][j]);
        }
        #pragma unroll
        for (int i = 0; i < 4; i++) {
            *(float4*)&Ssm[(ty*4+i)*64 + tx*4] = *(float4*)&s[i][0];
        }
        __syncthreads();

        // Online softmax: warp w handles rows 8w..8w+7
        #pragma unroll
        for (int rr = 0; rr < 8; rr++) {
            const int r = warp*8 + rr;
            float s0 = Ssm[r*64 + lane];
            float s1 = Ssm[r*64 + lane + 32];
            float mx = fmaxf(s0, s1);
            #pragma unroll
            for (int off = 16; off > 0; off >>= 1)
                mx = fmaxf(mx, __shfl_xor_sync(0xffffffffu, mx, off));
            const float m_old = m_s[r];
            const float m_new = fmaxf(m_old, mx);
            float p0 = __expf(s0 - m_new);
            float p1 = __expf(s1 - m_new);
            float sum = p0 + p1;
            #pragma unroll
            for (int off = 16; off > 0; off >>= 1)
                sum += __shfl_xor_sync(0xffffffffu, sum, off);
            Ssm[r*64 + lane]      = p0;
            Ssm[r*64 + lane + 32] = p1;
            if (lane == 0) {
                const float al = __expf(m_old - m_new);
                alpha_s[r] = al;
                l_s[r] = l_s[r]*al + sum;
                m_s[r] = m_new;
            }
        }
        __syncthreads();

        // Rescale O, then O += P @ V
        float al[4];
        #pragma unroll
        for (int i = 0; i < 4; i++) al[i] = alpha_s[ty*4 + i];
        #pragma unroll
        for (int i = 0; i < 4; i++)
            #pragma unroll
            for (int j = 0; j < 4; j++) o[i][j] *= al[i];

        #pragma unroll 8
        for (int c = 0; c < 64; c++) {
            float vb[4];
            *(float4*)&vb[0] = *(const float4*)&Vs[c*64 + tx*4];
            #pragma unroll
            for (int i = 0; i < 4; i++) {
                const float pv = Ssm[(ty*4+i)*64 + c];
                #pragma unroll
                for (int j = 0; j < 4; j++)
                    o[i][j] = fmaf(pv, vb[j], o[i][j]);
            }
        }
    }
    __syncthreads();

    // Normalize and store
    #pragma unroll
    for (int i = 0; i < 4; i++) {
        const int r = ty*4 + i;
        const float inv_l = 1.f / l_s[r];
        float4 res;
        res.x = o[i][0]*inv_l; res.y = o[i][1]*inv_l;
        res.z = o[i][2]*inv_l; res.w = o[i][3]*inv_l;
        *(float4*)&Og[r*HDIM + tx*4] = res;
    }
}

// ---------------------------------------------------------------------------
// Kernel 3: output projection.  out[m][c] = sum_k A2[m][k]*Wo[c][k] + bo[c]
// where A2[m][k] gathers g_A from [b][h][n][d] layout.
// ---------------------------------------------------------------------------
__global__ __launch_bounds__(256) void out_gemm(
    const float* __restrict__ Wo, const float* __restrict__ bo,
    float* __restrict__ out)
{
    __shared__ float As[16][128];
    __shared__ float Bs[16][128];

    const int tid = threadIdx.x;
    const int tx = tid & 15, ty = tid >> 4;
    const int m0 = blockIdx.y * 128;
    const int n0 = blockIdx.x * 128;
    const int lr = tid >> 2;
    const int lk = (tid & 3) << 2;

    float acc[8][8];
    #pragma unroll
    for (int i = 0; i < 8; i++)
        #pragma unroll
        for (int j = 0; j < 8; j++) acc[i][j] = 0.f;

    for (int k0 = 0; k0 < EMBED; k0 += 16) {
        const int h  = (k0 + lk) >> 6;
        const int dd = (k0 + lk) & 63;
        const int m_a = m0 + lr;
        const int b0_ = m_a >> 10,  nn0 = m_a & 1023;
        const int m_b = m0 + lr + 64;
        const int b1_ = m_b >> 10,  nn1 = m_b & 1023;
        float4 a0 = *(const float4*)&g_A[(((size_t)b0_*NHEADS + h)*SEQ + nn0)*HDIM + dd];
        float4 a1 = *(const float4*)&g_A[(((size_t)b1_*NHEADS + h)*SEQ + nn1)*HDIM + dd];
        float4 b0 = *(const float4*)&Wo[(size_t)(n0+lr   )*EMBED + k0 + lk];
        float4 b1 = *(const float4*)&Wo[(size_t)(n0+lr+64)*EMBED + k0 + lk];
        __syncthreads();
        As[lk+0][lr]    = a0.x; As[lk+1][lr]    = a0.y; As[lk+2][lr]    = a0.z; As[lk+3][lr]    = a0.w;
        As[lk+0][lr+64] = a1.x; As[lk+1][lr+64] = a1.y; As[lk+2][lr+64] = a1.z; As[lk+3][lr+64] = a1.w;
        Bs[lk+0][lr]    = b0.x; Bs[lk+1][lr]    = b0.y; Bs[lk+2][lr]    = b0.z; Bs[lk+3][lr]    = b0.w;
        Bs[lk+0][lr+64] = b1.x; Bs[lk+1][lr+64] = b1.y; Bs[lk+2][lr+64] = b1.z; Bs[lk+3][lr+64] = b1.w;
        __syncthreads();
        #pragma unroll
        for (int kk = 0; kk < 16; kk++) {
            float ra[8], rb[8];
            *(float4*)&ra[0] = *(const float4*)&As[kk][ty*8];
            *(float4*)&ra[4] = *(const float4*)&As[kk][ty*8+4];
            *(float4*)&rb[0] = *(const float4*)&Bs[kk][tx*8];
            *(float4*)&rb[4] = *(const float4*)&Bs[kk][tx*8+4];
            #pragma unroll
            for (int i = 0; i < 8; i++)
                #pragma unroll
                for (int j = 0; j < 8; j++)
                    acc[i][j] = fmaf(ra[i], rb[j], acc[i][j]);
        }
    }

    // Epilogue: row-major out + bias, float4 stores
    float bb[8];
    #pragma unroll
    for (int j = 0; j < 8; j++) bb[j] = bo[n0 + tx*8 + j];
    #pragma unroll
    for (int i = 0; i < 8; i++) {
        const int m = m0 + ty*8 + i;
        float r0[4], r1[4];
        #pragma unroll
        for (int j = 0; j < 4; j++) { r0[j] = acc[i][j] + bb[j]; r1[j] = acc[i][j+4] + bb[j+4]; }
        *(float4*)&out[(size_t)m*EMBED + n0 + tx*8]     = *(float4*)&r0[0];
        *(float4*)&out[(size_t)m*EMBED + n0 + tx*8 + 4] = *(float4*)&r1[0];
    }
}

// ---------------------------------------------------------------------------
extern "C" void kernel_launch(void* const* d_in, const int* in_sizes, int n_in,
                              void* d_out, int out_size)
{
    const float* x  = (const float*)d_in[0];
    const float* Wq = (const float*)d_in[1];
    const float* bq = (const float*)d_in[2];
    const float* Wk = (const float*)d_in[3];
    const float* bk = (const float*)d_in[4];
    const float* Wv = (const float*)d_in[5];
    const float* bv = (const float*)d_in[6];
    const float* Wo = (const float*)d_in[7];
    const float* bo = (const float*)d_in[8];
    float* out = (float*)d_out;

    // QKV projections
    dim3 g1(EMBED/128, MTOT/128, 3);
    qkv_gemm<<<g1, 256>>>(x, Wq, bq, Wk, bk, Wv, bv);

    // Attention
    const int smem_attn = (4*4096 + 3*64) * (int)sizeof(float);   // 66304 B
    cudaFuncSetAttribute(attn_kernel, cudaFuncAttributeMaxDynamicSharedMemorySize, smem_attn);
    dim3 g2(SEQ/64, BHEADS);
    attn_kernel<<<g2, 256, smem_attn>>>();

    // Output projection
    dim3 g3(EMBED/128, MTOT/128);
    out_gemm<<<g3, 256>>>(Wo, bo, out);
}

// round 4
// speedup vs baseline: 1.3631x; 1.3631x over previous
#include <cuda_runtime.h>
#include <math.h>

#define EMBED   768
#define NHEADS  12
#define HDIM    64
#define BATCH   16
#define SEQ     1024
#define MTOT    (BATCH*SEQ)      // 16384
#define BHEADS  (BATCH*NHEADS)   // 192
#define ATT_SCALE 0.125f

// Scratch (allocation-free rule: __device__ globals)
__device__ float g_Q[BHEADS*SEQ*HDIM];   // [bh][n][d]
__device__ float g_K[BHEADS*SEQ*HDIM];
__device__ float g_V[BHEADS*SEQ*HDIM];
__device__ float g_A[BHEADS*SEQ*HDIM];   // attention output

// ---------------------------------------------------------------------------
// helpers
// ---------------------------------------------------------------------------
__device__ __forceinline__ unsigned f2tf(float f) {
    unsigned u;
    asm("cvt.rna.tf32.f32 %0, %1;" : "=r"(u) : "f"(f));
    return u;
}

// D += A*B   (m16n8k8 tf32, row.col)
__device__ __forceinline__ void mma8(float* d, const unsigned* a, const unsigned* b) {
    asm volatile(
        "mma.sync.aligned.m16n8k8.row.col.f32.tf32.tf32.f32 "
        "{%0,%1,%2,%3}, {%4,%5,%6,%7}, {%8,%9}, {%0,%1,%2,%3};"
        : "+f"(d[0]), "+f"(d[1]), "+f"(d[2]), "+f"(d[3])
        : "r"(a[0]), "r"(a[1]), "r"(a[2]), "r"(a[3]), "r"(b[0]), "r"(b[1]));
}

// ---------------------------------------------------------------------------
// TF32 tensor-core GEMM: C[m][c] = sum_k A[m][k]*W[c][k] + bias[c]
// CTA tile 128x128, ktile 32, 8 warps each 64x32.
// smem layout [k][row + pad] (stride 136 floats).
// ---------------------------------------------------------------------------
#define KSTR 136

__device__ __forceinline__ void gemm_fill(unsigned* Sm, const float* src,
                                          int row0, int k0, int ld, int tid) {
    // 128 rows x 32 k = 1024 float4, 256 threads -> 4 each
    #pragma unroll
    for (int it = 0; it < 4; it++) {
        int lin = tid + 256*it;
        int rr = lin >> 3;            // 0..127
        int kq = lin & 7;             // 0..7 (float4 slot in k)
        const float4 v = *(const float4*)&src[(size_t)(row0+rr)*ld + k0 + kq*4];
        float vv[4] = {v.x, v.y, v.z, v.w};
        #pragma unroll
        for (int c = 0; c < 4; c++) {
            int cc = (c + kq) & 3;    // rotate to avoid bank conflicts
            Sm[(kq*4 + cc)*KSTR + rr] = f2tf(vv[cc]);
        }
    }
}

__global__ __launch_bounds__(256) void qkv_gemm_tc(
    const float* __restrict__ x,
    const float* __restrict__ Wq, const float* __restrict__ bq,
    const float* __restrict__ Wk, const float* __restrict__ bk,
    const float* __restrict__ Wv, const float* __restrict__ bv)
{
    const int p = blockIdx.z;
    const float* __restrict__ W    = (p==0) ? Wq : (p==1 ? Wk : Wv);
    const float* __restrict__ bias = (p==0) ? bq : (p==1 ? bk : bv);
    float* __restrict__ outp       = (p==0) ? g_Q : (p==1 ? g_K : g_V);

    __shared__ unsigned As[32*KSTR];
    __shared__ unsigned Bs[32*KSTR];

    const int tid  = threadIdx.x;
    const int w    = tid >> 5;
    const int lane = tid & 31;
    const int g    = lane >> 2;
    const int s    = lane & 3;
    const int wm   = (w & 1) * 64;
    const int wn   = (w >> 1) * 32;
    const int m0   = blockIdx.y * 128;
    const int n0   = blockIdx.x * 128;

    float acc[4][4][4];
    #pragma unroll
    for (int i = 0; i < 4; i++)
        #pragma unroll
        for (int j = 0; j < 4; j++)
            #pragma unroll
            for (int c = 0; c < 4; c++) acc[i][j][c] = 0.f;

    for (int k0 = 0; k0 < EMBED; k0 += 32) {
        __syncthreads();
        gemm_fill(As, x, m0, k0, EMBED, tid);
        gemm_fill(Bs, W, n0, k0, EMBED, tid);
        __syncthreads();
        #pragma unroll
        for (int kt = 0; kt < 4; kt++) {
            const int kk = kt * 8;
            unsigned a[4][4], b[4][2];
            #pragma unroll
            for (int i = 0; i < 4; i++) {
                const int base = (kk + s)*KSTR + wm + 16*i + g;
                a[i][0] = As[base];
                a[i][1] = As[base + 8];
                a[i][2] = As[base + 4*KSTR];
                a[i][3] = As[base + 4*KSTR + 8];
            }
            #pragma unroll
            for (int j = 0; j < 4; j++) {
                const int base = (kk + s)*KSTR + wn + 8*j + g;
                b[j][0] = Bs[base];
                b[j][1] = Bs[base + 4*KSTR];
            }
            #pragma unroll
            for (int i = 0; i < 4; i++)
                #pragma unroll
                for (int j = 0; j < 4; j++)
                    mma8(acc[i][j], a[i], b[j]);
        }
    }

    // Epilogue: scatter to [b][h][n][d] with bias, float2 stores
    #pragma unroll
    for (int i = 0; i < 4; i++) {
        const int m  = m0 + wm + 16*i + g;
        const int b_ = m >> 10;
        const int nn = m & 1023;
        #pragma unroll
        for (int j = 0; j < 4; j++) {
            const int c  = n0 + wn + 8*j + 2*s;
            const int h  = c >> 6;
            const int d  = c & 63;
            const float b0v = bias[c], b1v = bias[c+1];
            float2 v0 = make_float2(acc[i][j][0] + b0v, acc[i][j][1] + b1v);
            float2 v1 = make_float2(acc[i][j][2] + b0v, acc[i][j][3] + b1v);
            *(float2*)&outp[(((size_t)b_*NHEADS + h)*SEQ + nn    )*HDIM + d] = v0;
            *(float2*)&outp[(((size_t)b_*NHEADS + h)*SEQ + nn + 8)*HDIM + d] = v1;
        }
    }
}

__global__ __launch_bounds__(256) void out_gemm_tc(
    const float* __restrict__ Wo, const float* __restrict__ bo,
    float* __restrict__ out)
{
    __shared__ unsigned As[32*KSTR];
    __shared__ unsigned Bs[32*KSTR];

    const int tid  = threadIdx.x;
    const int w    = tid >> 5;
    const int lane = tid & 31;
    const int g    = lane >> 2;
    const int s    = lane & 3;
    const int wm   = (w & 1) * 64;
    const int wn   = (w >> 1) * 32;
    const int m0   = blockIdx.y * 128;
    const int n0   = blockIdx.x * 128;

    float acc[4][4][4];
    #pragma unroll
    for (int i = 0; i < 4; i++)
        #pragma unroll
        for (int j = 0; j < 4; j++)
            #pragma unroll
            for (int c = 0; c < 4; c++) acc[i][j][c] = 0.f;

    for (int k0 = 0; k0 < EMBED; k0 += 32) {
        __syncthreads();
        // A fill: gather from g_A [b][h][n][d]
        #pragma unroll
        for (int it = 0; it < 4; it++) {
            int lin = tid + 256*it;
            int rr = lin >> 3;
            int kq = lin & 7;
            const int m  = m0 + rr;
            const int b_ = m >> 10;
            const int nn = m & 1023;
            const int k  = k0 + kq*4;
            const int h  = k >> 6;
            const int d  = k & 63;
            const float4 v = *(const float4*)&g_A[(((size_t)b_*NHEADS + h)*SEQ + nn)*HDIM + d];
            float vv[4] = {v.x, v.y, v.z, v.w};
            #pragma unroll
            for (int c = 0; c < 4; c++) {
                int cc = (c + kq) & 3;
                As[(kq*4 + cc)*KSTR + rr] = f2tf(vv[cc]);
            }
        }
        gemm_fill(Bs, Wo, n0, k0, EMBED, tid);
        __syncthreads();
        #pragma unroll
        for (int kt = 0; kt < 4; kt++) {
            const int kk = kt * 8;
            unsigned a[4][4], b[4][2];
            #pragma unroll
            for (int i = 0; i < 4; i++) {
                const int base = (kk + s)*KSTR + wm + 16*i + g;
                a[i][0] = As[base];
                a[i][1] = As[base + 8];
                a[i][2] = As[base + 4*KSTR];
                a[i][3] = As[base + 4*KSTR + 8];
            }
            #pragma unroll
            for (int j = 0; j < 4; j++) {
                const int base = (kk + s)*KSTR + wn + 8*j + g;
                b[j][0] = Bs[base];
                b[j][1] = Bs[base + 4*KSTR];
            }
            #pragma unroll
            for (int i = 0; i < 4; i++)
                #pragma unroll
                for (int j = 0; j < 4; j++)
                    mma8(acc[i][j], a[i], b[j]);
        }
    }

    // Epilogue: row-major out + bias
    #pragma unroll
    for (int i = 0; i < 4; i++) {
        const int m = m0 + wm + 16*i + g;
        #pragma unroll
        for (int j = 0; j < 4; j++) {
            const int c = n0 + wn + 8*j + 2*s;
            const float b0v = bo[c], b1v = bo[c+1];
            float2 v0 = make_float2(acc[i][j][0] + b0v, acc[i][j][1] + b1v);
            float2 v1 = make_float2(acc[i][j][2] + b0v, acc[i][j][3] + b1v);
            *(float2*)&out[(size_t)m*EMBED + c]       = v0;
            *(float2*)&out[(size_t)(m+8)*EMBED + c]   = v1;
        }
    }
}

// ---------------------------------------------------------------------------
// Flash attention, tensor cores. Br=128 q-rows per CTA, Bc=64 keys per tile.
// 256 threads / 8 warps, warp w owns q-rows [16w, 16w+16).
// smem: sQ [64][136] (then reused as sP [128][72]) | sK [64][72] | sV [64][72]
// ---------------------------------------------------------------------------
#define PSTR 72

__global__ __launch_bounds__(256) void attn_tc()
{
    extern __shared__ unsigned smu[];
    unsigned* sQ = smu;                    // [d=64][m+pad=136]  (8704 words)
    unsigned* sP = smu;                    // [m=128][key+pad=72] (9216 words)
    unsigned* sK = smu + 9216;             // [d=64][key+pad=72]  transposed
    unsigned* sV = sK + 64*PSTR;           // [key=64][d+pad=72]  natural

    const int tid  = threadIdx.x;
    const int w    = tid >> 5;
    const int lane = tid & 31;
    const int g    = lane >> 2;
    const int s    = lane & 3;
    const int bh   = blockIdx.y;
    const int q0   = blockIdx.x * 128;
    const int r0   = 16*w + g;
    const int r1   = r0 + 8;

    const float* __restrict__ Qg = g_Q + ((size_t)bh*SEQ + q0)*HDIM;
    const float* __restrict__ Kg = g_K + (size_t)bh*SEQ*HDIM;
    const float* __restrict__ Vg = g_V + (size_t)bh*SEQ*HDIM;
    float* __restrict__ Og = g_A + ((size_t)bh*SEQ + q0)*HDIM;

    // ---- load Q (128 x 64), transpose to [d][m], pre-scale, tf32 ----
    #pragma unroll
    for (int it = 0; it < 8; it++) {
        int lin = tid + 256*it;          // 2048 float4
        int rr = lin >> 4;               // 0..127
        int dq = lin & 15;               // float4 slot in d
        const float4 q = *(const float4*)&Qg[rr*HDIM + dq*4];
        float qq[4] = {q.x*ATT_SCALE, q.y*ATT_SCALE, q.z*ATT_SCALE, q.w*ATT_SCALE};
        #pragma unroll
        for (int c = 0; c < 4; c++) {
            int cc = (c + dq) & 3;
            sQ[(dq*4 + cc)*KSTR + rr] = f2tf(qq[cc]);
        }
    }
    __syncthreads();

    // cache Q A-fragments in registers (whole warp tile, k=64 -> 8 steps)
    unsigned qa[8][4];
    #pragma unroll
    for (int kt = 0; kt < 8; kt++) {
        const int base = (8*kt + s)*KSTR + 16*w + g;
        qa[kt][0] = sQ[base];
        qa[kt][1] = sQ[base + 8];
        qa[kt][2] = sQ[base + 4*KSTR];
        qa[kt][3] = sQ[base + 4*KSTR + 8];
    }

    float o[8][4];
    #pragma unroll
    for (int j = 0; j < 8; j++)
        #pragma unroll
        for (int c = 0; c < 4; c++) o[j][c] = 0.f;
    float mr0 = -1e30f, mr1 = -1e30f, lr0 = 0.f, lr1 = 0.f;

    for (int t = 0; t < SEQ/64; t++) {
        __syncthreads();   // prev P/V consumed; Q frags read (first iter)
        // fill K transposed [d][key] (tf32) and V natural [key][d] (tf32)
        #pragma unroll
        for (int it = 0; it < 4; it++) {
            int lin = tid + 256*it;      // 1024 float4
            int rr = lin >> 4;           // key 0..63
            int dq = lin & 15;
            const float4 k4 = *(const float4*)&Kg[(size_t)(t*64 + rr)*HDIM + dq*4];
            float kk4[4] = {k4.x, k4.y, k4.z, k4.w};
            #pragma unroll
            for (int c = 0; c < 4; c++) {
                int cc = (c + dq) & 3;
                sK[(dq*4 + cc)*PSTR + rr] = f2tf(kk4[cc]);
            }
            const float4 v4 = *(const float4*)&Vg[(size_t)(t*64 + rr)*HDIM + dq*4];
            uint4 vt = make_uint4(f2tf(v4.x), f2tf(v4.y), f2tf(v4.z), f2tf(v4.w));
            *(uint4*)&sV[rr*PSTR + dq*4] = vt;
        }
        __syncthreads();

        // ---- S = Q @ K^T (128x64) ----
        float sc[8][4];
        #pragma unroll
        for (int j = 0; j < 8; j++)
            #pragma unroll
            for (int c = 0; c < 4; c++) sc[j][c] = 0.f;
        #pragma unroll
        for (int kt = 0; kt < 8; kt++) {
            unsigned kb[8][2];
            #pragma unroll
            for (int j = 0; j < 8; j++) {
                const int base = (8*kt + s)*PSTR + 8*j + g;
                kb[j][0] = sK[base];
                kb[j][1] = sK[base + 4*PSTR];
            }
            #pragma unroll
            for (int j = 0; j < 8; j++)
                mma8(sc[j], qa[kt], kb[j]);
        }

        // ---- online softmax (register-resident, quad reductions) ----
        float mx0 = -1e30f, mx1 = -1e30f;
        #pragma unroll
        for (int j = 0; j < 8; j++) {
            mx0 = fmaxf(mx0, fmaxf(sc[j][0], sc[j][1]));
            mx1 = fmaxf(mx1, fmaxf(sc[j][2], sc[j][3]));
        }
        mx0 = fmaxf(mx0, __shfl_xor_sync(0xffffffffu, mx0, 1));
        mx0 = fmaxf(mx0, __shfl_xor_sync(0xffffffffu, mx0, 2));
        mx1 = fmaxf(mx1, __shfl_xor_sync(0xffffffffu, mx1, 1));
        mx1 = fmaxf(mx1, __shfl_xor_sync(0xffffffffu, mx1, 2));
        const float mn0 = fmaxf(mr0, mx0);
        const float mn1 = fmaxf(mr1, mx1);
        const float al0 = __expf(mr0 - mn0);
        const float al1 = __expf(mr1 - mn1);
        mr0 = mn0; mr1 = mn1;
        float sum0 = 0.f, sum1 = 0.f;
        #pragma unroll
        for (int j = 0; j < 8; j++) {
            sc[j][0] = __expf(sc[j][0] - mn0);
            sc[j][1] = __expf(sc[j][1] - mn0);
            sc[j][2] = __expf(sc[j][2] - mn1);
            sc[j][3] = __expf(sc[j][3] - mn1);
            sum0 += sc[j][0] + sc[j][1];
            sum1 += sc[j][2] + sc[j][3];
        }
        sum0 += __shfl_xor_sync(0xffffffffu, sum0, 1);
        sum0 += __shfl_xor_sync(0xffffffffu, sum0, 2);
        sum1 += __shfl_xor_sync(0xffffffffu, sum1, 1);
        sum1 += __shfl_xor_sync(0xffffffffu, sum1, 2);
        lr0 = lr0*al0 + sum0;
        lr1 = lr1*al1 + sum1;
        #pragma unroll
        for (int j = 0; j < 8; j++) {
            o[j][0] *= al0; o[j][1] *= al0;
            o[j][2] *= al1; o[j][3] *= al1;
        }

        // ---- store P (tf32) to smem for PV mma ----
        #pragma unroll
        for (int j = 0; j < 8; j++) {
            *(uint2*)&sP[r0*PSTR + 8*j + 2*s] = make_uint2(f2tf(sc[j][0]), f2tf(sc[j][1]));
            *(uint2*)&sP[r1*PSTR + 8*j + 2*s] = make_uint2(f2tf(sc[j][2]), f2tf(sc[j][3]));
        }
        __syncthreads();

        // ---- O += P @ V ----
        #pragma unroll
        for (int kt = 0; kt < 8; kt++) {
            unsigned pa[4];
            pa[0] = sP[r0*PSTR + 8*kt + s];
            pa[1] = sP[r1*PSTR + 8*kt + s];
            pa[2] = sP[r0*PSTR + 8*kt + s + 4];
            pa[3] = sP[r1*PSTR + 8*kt + s + 4];
            #pragma unroll
            for (int j = 0; j < 8; j++) {
                unsigned vb[2];
                const int base = (8*kt + s)*PSTR + 8*j + g;
                vb[0] = sV[base];
                vb[1] = sV[base + 4*PSTR];
                mma8(o[j], pa, vb);
            }
        }
    }

    // ---- normalize + store ----
    const float il0 = 1.f / lr0;
    const float il1 = 1.f / lr1;
    #pragma unroll
    for (int j = 0; j < 8; j++) {
        *(float2*)&Og[r0*HDIM + 8*j + 2*s] = make_float2(o[j][0]*il0, o[j][1]*il0);
        *(float2*)&Og[r1*HDIM + 8*j + 2*s] = make_float2(o[j][2]*il1, o[j][3]*il1);
    }
}

// ---------------------------------------------------------------------------
extern "C" void kernel_launch(void* const* d_in, const int* in_sizes, int n_in,
                              void* d_out, int out_size)
{
    const float* x  = (const float*)d_in[0];
    const float* Wq = (const float*)d_in[1];
    const float* bq = (const float*)d_in[2];
    const float* Wk = (const float*)d_in[3];
    const float* bk = (const float*)d_in[4];
    const float* Wv = (const float*)d_in[5];
    const float* bv = (const float*)d_in[6];
    const float* Wo = (const float*)d_in[7];
    const float* bo = (const float*)d_in[8];
    float* out = (float*)d_out;

    // QKV projections (TF32 tensor cores)
    dim3 g1(EMBED/128, MTOT/128, 3);
    qkv_gemm_tc<<<g1, 256>>>(x, Wq, bq, Wk, bk, Wv, bv);

    // Flash attention (TF32 tensor cores)
    const int smem_attn = (9216 + 64*PSTR + 64*PSTR) * (int)sizeof(unsigned); // 73728 B
    cudaFuncSetAttribute(attn_tc, cudaFuncAttributeMaxDynamicSharedMemorySize, smem_attn);
    dim3 g2(SEQ/128, BHEADS);
    attn_tc<<<g2, 256, smem_attn>>>();

    // Output projection
    dim3 g3(EMBED/128, MTOT/128);
    out_gemm_tc<<<g3, 256>>>(Wo, bo, out);
}

// round 7
// speedup vs baseline: 1.8489x; 1.3564x over previous
#include <cuda_runtime.h>
#include <math.h>

#define EMBED   768
#define NHEADS  12
#define HDIM    64
#define BATCH   16
#define SEQ     1024
#define MTOT    (BATCH*SEQ)      // 16384
#define BHEADS  (BATCH*NHEADS)   // 192
#define ATT_SCALE 0.125f

// Scratch (allocation-free rule: __device__ globals)
__device__ float g_Q[BHEADS*SEQ*HDIM];   // [bh][n][d]
__device__ float g_K[BHEADS*SEQ*HDIM];
__device__ float g_V[BHEADS*SEQ*HDIM];
__device__ float g_A[BHEADS*SEQ*HDIM];   // attention output

// ---------------------------------------------------------------------------
// helpers
// ---------------------------------------------------------------------------
__device__ __forceinline__ unsigned f2tf(float f) {
    unsigned u;
    asm("cvt.rna.tf32.f32 %0, %1;" : "=r"(u) : "f"(f));
    return u;
}

// D += A*B   (m16n8k8 tf32, row.col)
__device__ __forceinline__ void mma8(float* d, const unsigned* a, const unsigned* b) {
    asm volatile(
        "mma.sync.aligned.m16n8k8.row.col.f32.tf32.tf32.f32 "
        "{%0,%1,%2,%3}, {%4,%5,%6,%7}, {%8,%9}, {%0,%1,%2,%3};"
        : "+f"(d[0]), "+f"(d[1]), "+f"(d[2]), "+f"(d[3])
        : "r"(a[0]), "r"(a[1]), "r"(a[2]), "r"(a[3]), "r"(b[0]), "r"(b[1]));
}

// ---------------------------------------------------------------------------
// TF32 tensor-core GEMM: C[m][c] = sum_k A[m][k]*W[c][k] + bias[c]
// CTA tile 128x128, ktile 32, 8 warps each 64x32.
// Double-buffered smem [k][row+pad] (stride 136), register prefetch of LDGs.
// ---------------------------------------------------------------------------
#define KSTR  136
#define TILEW (32*KSTR)          // words per tile buffer

__device__ __forceinline__ void gemm_ldg(float4* r, const float* __restrict__ src,
                                         int row0, int k0, int ld, int tid) {
    #pragma unroll
    for (int it = 0; it < 4; it++) {
        int lin = tid + 256*it;
        int rr = lin >> 3;            // 0..127
        int kq = lin & 7;             // float4 slot in k
        r[it] = *(const float4*)&src[(size_t)(row0+rr)*ld + k0 + kq*4];
    }
}

__device__ __forceinline__ void gemm_sts(unsigned* Sm, const float4* r, int tid) {
    #pragma unroll
    for (int it = 0; it < 4; it++) {
        int lin = tid + 256*it;
        int rr = lin >> 3;
        int kq = lin & 7;
        float vv[4] = {r[it].x, r[it].y, r[it].z, r[it].w};
        #pragma unroll
        for (int c = 0; c < 4; c++) {
            int cc = (c + kq) & 3;    // rotate to avoid bank conflicts
            Sm[(kq*4 + cc)*KSTR + rr] = f2tf(vv[cc]);
        }
    }
}

__device__ __forceinline__ void gemm_compute(const unsigned* As, const unsigned* Bs,
                                             float acc[4][4][4], int wm, int wn,
                                             int g, int s) {
    #pragma unroll
    for (int kt = 0; kt < 4; kt++) {
        const int kk = kt * 8;
        unsigned a[4][4], b[4][2];
        #pragma unroll
        for (int i = 0; i < 4; i++) {
            const int base = (kk + s)*KSTR + wm + 16*i + g;
            a[i][0] = As[base];
            a[i][1] = As[base + 8];
            a[i][2] = As[base + 4*KSTR];
            a[i][3] = As[base + 4*KSTR + 8];
        }
        #pragma unroll
        for (int j = 0; j < 4; j++) {
            const int base = (kk + s)*KSTR + wn + 8*j + g;
            b[j][0] = Bs[base];
            b[j][1] = Bs[base + 4*KSTR];
        }
        #pragma unroll
        for (int i = 0; i < 4; i++)
            #pragma unroll
            for (int j = 0; j < 4; j++)
                mma8(acc[i][j], a[i], b[j]);
    }
}

__global__ __launch_bounds__(256) void qkv_gemm_tc(
    const float* __restrict__ x,
    const float* __restrict__ Wq, const float* __restrict__ bq,
    const float* __restrict__ Wk, const float* __restrict__ bk,
    const float* __restrict__ Wv, const float* __restrict__ bv)
{
    const int p = blockIdx.z;
    const float* __restrict__ W    = (p==0) ? Wq : (p==1 ? Wk : Wv);
    const float* __restrict__ bias = (p==0) ? bq : (p==1 ? bk : bv);
    float* __restrict__ outp       = (p==0) ? g_Q : (p==1 ? g_K : g_V);

    extern __shared__ unsigned smg[];
    unsigned* Asb = smg;                 // 2 buffers
    unsigned* Bsb = smg + 2*TILEW;

    const int tid  = threadIdx.x;
    const int w    = tid >> 5;
    const int lane = tid & 31;
    const int g    = lane >> 2;
    const int s    = lane & 3;
    const int wm   = (w & 1) * 64;
    const int wn   = (w >> 1) * 32;
    const int m0   = blockIdx.y * 128;
    const int n0   = blockIdx.x * 128;

    float acc[4][4][4];
    #pragma unroll
    for (int i = 0; i < 4; i++)
        #pragma unroll
        for (int j = 0; j < 4; j++)
            #pragma unroll
            for (int c = 0; c < 4; c++) acc[i][j][c] = 0.f;

    float4 ra[4], rb[4];
    gemm_ldg(ra, x, m0, 0, EMBED, tid);
    gemm_ldg(rb, W, n0, 0, EMBED, tid);
    gemm_sts(Asb, ra, tid);
    gemm_sts(Bsb, rb, tid);
    __syncthreads();

    int buf = 0;
    for (int k0 = 0; k0 < EMBED; k0 += 32) {
        const bool more = (k0 + 32) < EMBED;
        if (more) {
            gemm_ldg(ra, x, m0, k0+32, EMBED, tid);
            gemm_ldg(rb, W, n0, k0+32, EMBED, tid);
        }
        gemm_compute(Asb + buf*TILEW, Bsb + buf*TILEW, acc, wm, wn, g, s);
        if (more) {
            gemm_sts(Asb + (buf^1)*TILEW, ra, tid);
            gemm_sts(Bsb + (buf^1)*TILEW, rb, tid);
            __syncthreads();
        }
        buf ^= 1;
    }

    // Epilogue: scatter to [b][h][n][d] with bias, float2 stores
    #pragma unroll
    for (int i = 0; i < 4; i++) {
        const int m  = m0 + wm + 16*i + g;
        const int b_ = m >> 10;
        const int nn = m & 1023;
        #pragma unroll
        for (int j = 0; j < 4; j++) {
            const int c  = n0 + wn + 8*j + 2*s;
            const int h  = c >> 6;
            const int d  = c & 63;
            const float b0v = bias[c], b1v = bias[c+1];
            float2 v0 = make_float2(acc[i][j][0] + b0v, acc[i][j][1] + b1v);
            float2 v1 = make_float2(acc[i][j][2] + b0v, acc[i][j][3] + b1v);
            *(float2*)&outp[(((size_t)b_*NHEADS + h)*SEQ + nn    )*HDIM + d] = v0;
            *(float2*)&outp[(((size_t)b_*NHEADS + h)*SEQ + nn + 8)*HDIM + d] = v1;
        }
    }
}

__device__ __forceinline__ void outA_ldg(float4* r, int m0, int k0, int tid) {
    #pragma unroll
    for (int it = 0; it < 4; it++) {
        int lin = tid + 256*it;
        int rr = lin >> 3;
        int kq = lin & 7;
        const int m  = m0 + rr;
        const int b_ = m >> 10;
        const int nn = m & 1023;
        const int k  = k0 + kq*4;
        const int h  = k >> 6;
        const int d  = k & 63;
        r[it] = *(const float4*)&g_A[(((size_t)b_*NHEADS + h)*SEQ + nn)*HDIM + d];
    }
}

__global__ __launch_bounds__(256) void out_gemm_tc(
    const float* __restrict__ Wo, const float* __restrict__ bo,
    float* __restrict__ out)
{
    extern __shared__ unsigned smg[];
    unsigned* Asb = smg;
    unsigned* Bsb = smg + 2*TILEW;

    const int tid  = threadIdx.x;
    const int w    = tid >> 5;
    const int lane = tid & 31;
    const int g    = lane >> 2;
    const int s    = lane & 3;
    const int wm   = (w & 1) * 64;
    const int wn   = (w >> 1) * 32;
    const int m0   = blockIdx.y * 128;
    const int n0   = blockIdx.x * 128;

    float acc[4][4][4];
    #pragma unroll
    for (int i = 0; i < 4; i++)
        #pragma unroll
        for (int j = 0; j < 4; j++)
            #pragma unroll
            for (int c = 0; c < 4; c++) acc[i][j][c] = 0.f;

    float4 ra[4], rb[4];
    outA_ldg(ra, m0, 0, tid);
    gemm_ldg(rb, Wo, n0, 0, EMBED, tid);
    gemm_sts(Asb, ra, tid);
    gemm_sts(Bsb, rb, tid);
    __syncthreads();

    int buf = 0;
    for (int k0 = 0; k0 < EMBED; k0 += 32) {
        const bool more = (k0 + 32) < EMBED;
        if (more) {
            outA_ldg(ra, m0, k0+32, tid);
            gemm_ldg(rb, Wo, n0, k0+32, EMBED, tid);
        }
        gemm_compute(Asb + buf*TILEW, Bsb + buf*TILEW, acc, wm, wn, g, s);
        if (more) {
            gemm_sts(Asb + (buf^1)*TILEW, ra, tid);
            gemm_sts(Bsb + (buf^1)*TILEW, rb, tid);
            __syncthreads();
        }
        buf ^= 1;
    }

    // Epilogue: row-major out + bias
    #pragma unroll
    for (int i = 0; i < 4; i++) {
        const int m = m0 + wm + 16*i + g;
        #pragma unroll
        for (int j = 0; j < 4; j++) {
            const int c = n0 + wn + 8*j + 2*s;
            const float b0v = bo[c], b1v = bo[c+1];
            float2 v0 = make_float2(acc[i][j][0] + b0v, acc[i][j][1] + b1v);
            float2 v1 = make_float2(acc[i][j][2] + b0v, acc[i][j][3] + b1v);
            *(float2*)&out[(size_t)m*EMBED + c]       = v0;
            *(float2*)&out[(size_t)(m+8)*EMBED + c]   = v1;
        }
    }
}

// ---------------------------------------------------------------------------
// Flash attention, tensor cores, double-buffered K/V with register prefetch.
// Br=128 q-rows/CTA, Bc=64 keys/tile, 256 threads / 8 warps.
// smem: sQ [64][136] (reused as sP [128][72]) | sK[2][64][72] | sV[2][64][72]
// ---------------------------------------------------------------------------
#define PSTR  72
#define KVW   (64*PSTR)

__global__ __launch_bounds__(256) void attn_tc()
{
    extern __shared__ unsigned smu[];
    unsigned* sQ = smu;                    // [d=64][m+pad=136]
    unsigned* sP = smu;                    // [m=128][key+pad=72]
    unsigned* sK = smu + 9216;             // 2 buffers [d][key+pad]
    unsigned* sV = sK + 2*KVW;             // 2 buffers [key][d+pad]

    const int tid  = threadIdx.x;
    const int w    = tid >> 5;
    const int lane = tid & 31;
    const int g    = lane >> 2;
    const int s    = lane & 3;
    const int bh   = blockIdx.y;
    const int q0   = blockIdx.x * 128;
    const int r0   = 16*w + g;
    const int r1   = r0 + 8;

    const float* __restrict__ Qg = g_Q + ((size_t)bh*SEQ + q0)*HDIM;
    const float* __restrict__ Kg = g_K + (size_t)bh*SEQ*HDIM;
    const float* __restrict__ Vg = g_V + (size_t)bh*SEQ*HDIM;
    float* __restrict__ Og = g_A + ((size_t)bh*SEQ + q0)*HDIM;

    float4 kreg[4], vreg[4];

    // prefetch KV tile 0
    #pragma unroll
    for (int it = 0; it < 4; it++) {
        int lin = tid + 256*it;
        int rr = lin >> 4, dq = lin & 15;
        kreg[it] = *(const float4*)&Kg[(size_t)rr*HDIM + dq*4];
        vreg[it] = *(const float4*)&Vg[(size_t)rr*HDIM + dq*4];
    }

    // ---- load Q (128 x 64), transpose to [d][m], pre-scale, tf32 ----
    #pragma unroll
    for (int it = 0; it < 8; it++) {
        int lin = tid + 256*it;
        int rr = lin >> 4;
        int dq = lin & 15;
        const float4 q = *(const float4*)&Qg[rr*HDIM + dq*4];
        float qq[4] = {q.x*ATT_SCALE, q.y*ATT_SCALE, q.z*ATT_SCALE, q.w*ATT_SCALE};
        #pragma unroll
        for (int c = 0; c < 4; c++) {
            int cc = (c + dq) & 3;
            sQ[(dq*4 + cc)*KSTR + rr] = f2tf(qq[cc]);
        }
    }

    // store KV tile 0 into buffer 0
    #pragma unroll
    for (int it = 0; it < 4; it++) {
        int lin = tid + 256*it;
        int rr = lin >> 4, dq = lin & 15;
        float kk4[4] = {kreg[it].x, kreg[it].y, kreg[it].z, kreg[it].w};
        #pragma unroll
        for (int c = 0; c < 4; c++) {
            int cc = (c + dq) & 3;
            sK[(dq*4 + cc)*PSTR + rr] = f2tf(kk4[cc]);
        }
        uint4 vt = make_uint4(f2tf(vreg[it].x), f2tf(vreg[it].y), f2tf(vreg[it].z), f2tf(vreg[it].w));
        *(uint4*)&sV[rr*PSTR + dq*4] = vt;
    }
    __syncthreads();

    // cache Q A-fragments in registers
    unsigned qa[8][4];
    #pragma unroll
    for (int kt = 0; kt < 8; kt++) {
        const int base = (8*kt + s)*KSTR + 16*w + g;
        qa[kt][0] = sQ[base];
        qa[kt][1] = sQ[base + 8];
        qa[kt][2] = sQ[base + 4*KSTR];
        qa[kt][3] = sQ[base + 4*KSTR + 8];
    }

    float o[8][4];
    #pragma unroll
    for (int j = 0; j < 8; j++)
        #pragma unroll
        for (int c = 0; c < 4; c++) o[j][c] = 0.f;
    float mr0 = -1e30f, mr1 = -1e30f, lr0 = 0.f, lr1 = 0.f;

    int buf = 0;
    for (int t = 0; t < SEQ/64; t++) {
        const bool more = (t + 1) < SEQ/64;
        // prefetch next KV tile into registers (hidden behind S + softmax)
        if (more) {
            #pragma unroll
            for (int it = 0; it < 4; it++) {
                int lin = tid + 256*it;
                int rr = lin >> 4, dq = lin & 15;
                kreg[it] = *(const float4*)&Kg[(size_t)((t+1)*64 + rr)*HDIM + dq*4];
                vreg[it] = *(const float4*)&Vg[(size_t)((t+1)*64 + rr)*HDIM + dq*4];
            }
        }

        const unsigned* sKb = sK + buf*KVW;
        const unsigned* sVb = sV + buf*KVW;

        // ---- S = Q @ K^T (128x64) ----
        float sc[8][4];
        #pragma unroll
        for (int j = 0; j < 8; j++)
            #pragma unroll
            for (int c = 0; c < 4; c++) sc[j][c] = 0.f;
        #pragma unroll
        for (int kt = 0; kt < 8; kt++) {
            unsigned kb[8][2];
            #pragma unroll
            for (int j = 0; j < 8; j++) {
                const int base = (8*kt + s)*PSTR + 8*j + g;
                kb[j][0] = sKb[base];
                kb[j][1] = sKb[base + 4*PSTR];
            }
            #pragma unroll
            for (int j = 0; j < 8; j++)
                mma8(sc[j], qa[kt], kb[j]);
        }

        // ---- online softmax (register-resident, quad reductions) ----
        float mx0 = -1e30f, mx1 = -1e30f;
        #pragma unroll
        for (int j = 0; j < 8; j++) {
            mx0 = fmaxf(mx0, fmaxf(sc[j][0], sc[j][1]));
            mx1 = fmaxf(mx1, fmaxf(sc[j][2], sc[j][3]));
        }
        mx0 = fmaxf(mx0, __shfl_xor_sync(0xffffffffu, mx0, 1));
        mx0 = fmaxf(mx0, __shfl_xor_sync(0xffffffffu, mx0, 2));
        mx1 = fmaxf(mx1, __shfl_xor_sync(0xffffffffu, mx1, 1));
        mx1 = fmaxf(mx1, __shfl_xor_sync(0xffffffffu, mx1, 2));
        const float mn0 = fmaxf(mr0, mx0);
        const float mn1 = fmaxf(mr1, mx1);
        const float al0 = __expf(mr0 - mn0);
        const float al1 = __expf(mr1 - mn1);
        mr0 = mn0; mr1 = mn1;
        float sum0 = 0.f, sum1 = 0.f;
        #pragma unroll
        for (int j = 0; j < 8; j++) {
            sc[j][0] = __expf(sc[j][0] - mn0);
            sc[j][1] = __expf(sc[j][1] - mn0);
            sc[j][2] = __expf(sc[j][2] - mn1);
            sc[j][3] = __expf(sc[j][3] - mn1);
            sum0 += sc[j][0] + sc[j][1];
            sum1 += sc[j][2] + sc[j][3];
        }
        sum0 += __shfl_xor_sync(0xffffffffu, sum0, 1);
        sum0 += __shfl_xor_sync(0xffffffffu, sum0, 2);
        sum1 += __shfl_xor_sync(0xffffffffu, sum1, 1);
        sum1 += __shfl_xor_sync(0xffffffffu, sum1, 2);
        lr0 = lr0*al0 + sum0;
        lr1 = lr1*al1 + sum1;
        #pragma unroll
        for (int j = 0; j < 8; j++) {
            o[j][0] *= al0; o[j][1] *= al0;
            o[j][2] *= al1; o[j][3] *= al1;
        }

        // barrier: previous PV (readers of sP and buf^1) must be done
        __syncthreads();

        // ---- store P (tf32) to smem + stage next KV into other buffer ----
        #pragma unroll
        for (int j = 0; j < 8; j++) {
            *(uint2*)&sP[r0*PSTR + 8*j + 2*s] = make_uint2(f2tf(sc[j][0]), f2tf(sc[j][1]));
            *(uint2*)&sP[r1*PSTR + 8*j + 2*s] = make_uint2(f2tf(sc[j][2]), f2tf(sc[j][3]));
        }
        if (more) {
            unsigned* sKn = sK + (buf^1)*KVW;
            unsigned* sVn = sV + (buf^1)*KVW;
            #pragma unroll
            for (int it = 0; it < 4; it++) {
                int lin = tid + 256*it;
                int rr = lin >> 4, dq = lin & 15;
                float kk4[4] = {kreg[it].x, kreg[it].y, kreg[it].z, kreg[it].w};
                #pragma unroll
                for (int c = 0; c < 4; c++) {
                    int cc = (c + dq) & 3;
                    sKn[(dq*4 + cc)*PSTR + rr] = f2tf(kk4[cc]);
                }
                uint4 vt = make_uint4(f2tf(vreg[it].x), f2tf(vreg[it].y), f2tf(vreg[it].z), f2tf(vreg[it].w));
                *(uint4*)&sVn[rr*PSTR + dq*4] = vt;
            }
        }
        __syncthreads();

        // ---- O += P @ V ----
        #pragma unroll
        for (int kt = 0; kt < 8; kt++) {
            unsigned pa[4];
            pa[0] = sP[r0*PSTR + 8*kt + s];
            pa[1] = sP[r1*PSTR + 8*kt + s];
            pa[2] = sP[r0*PSTR + 8*kt + s + 4];
            pa[3] = sP[r1*PSTR + 8*kt + s + 4];
            #pragma unroll
            for (int j = 0; j < 8; j++) {
                unsigned vb[2];
                const int base = (8*kt + s)*PSTR + 8*j + g;
                vb[0] = sVb[base];
                vb[1] = sVb[base + 4*PSTR];
                mma8(o[j], pa, vb);
            }
        }
        buf ^= 1;
    }

    // ---- normalize + store ----
    const float il0 = 1.f / lr0;
    const float il1 = 1.f / lr1;
    #pragma unroll
    for (int j = 0; j < 8; j++) {
        *(float2*)&Og[r0*HDIM + 8*j + 2*s] = make_float2(o[j][0]*il0, o[j][1]*il0);
        *(float2*)&Og[r1*HDIM + 8*j + 2*s] = make_float2(o[j][2]*il1, o[j][3]*il1);
    }
}

// ---------------------------------------------------------------------------
extern "C" void kernel_launch(void* const* d_in, const int* in_sizes, int n_in,
                              void* d_out, int out_size)
{
    const float* x  = (const float*)d_in[0];
    const float* Wq = (const float*)d_in[1];
    const float* bq = (const float*)d_in[2];
    const float* Wk = (const float*)d_in[3];
    const float* bk = (const float*)d_in[4];
    const float* Wv = (const float*)d_in[5];
    const float* bv = (const float*)d_in[6];
    const float* Wo = (const float*)d_in[7];
    const float* bo = (const float*)d_in[8];
    float* out = (float*)d_out;

    const int smem_gemm = 4*TILEW*(int)sizeof(unsigned);             // 69632 B
    const int smem_attn = (9216 + 4*KVW)*(int)sizeof(unsigned);      // 110592 B

    cudaFuncSetAttribute(qkv_gemm_tc, cudaFuncAttributeMaxDynamicSharedMemorySize, smem_gemm);
    cudaFuncSetAttribute(out_gemm_tc, cudaFuncAttributeMaxDynamicSharedMemorySize, smem_gemm);
    cudaFuncSetAttribute(attn_tc,     cudaFuncAttributeMaxDynamicSharedMemorySize, smem_attn);

    // QKV projections (TF32 tensor cores, pipelined)
    dim3 g1(EMBED/128, MTOT/128, 3);
    qkv_gemm_tc<<<g1, 256, smem_gemm>>>(x, Wq, bq, Wk, bk, Wv, bv);

    // Flash attention (TF32 tensor cores, pipelined)
    dim3 g2(SEQ/128, BHEADS);
    attn_tc<<<g2, 256, smem_attn>>>();

    // Output projection
    dim3 g3(EMBED/128, MTOT/128);
    out_gemm_tc<<<g3, 256, smem_gemm>>>(Wo, bo, out);
}

// round 11
// speedup vs baseline: 3.4651x; 1.8741x over previous
#include <cuda_runtime.h>
#include <math.h>

#define EMBED   768
#define NHEADS  12
#define HDIM    64
#define BATCH   16
#define SEQ     1024
#define MTOT    (BATCH*SEQ)      // 16384
#define BHEADS  (BATCH*NHEADS)   // 192
#define ATT_SCALE 0.125f

// Scratch (allocation-free rule: __device__ globals)
__device__ __align__(16) float g_Q[BHEADS*SEQ*HDIM];   // tf32-valued fp32
__device__ __align__(16) float g_K[BHEADS*SEQ*HDIM];
__device__ __align__(16) float g_V[BHEADS*SEQ*HDIM];
__device__ __align__(16) float g_A[BHEADS*SEQ*HDIM];   // tf32-valued fp32

// Pre-converted tf32 operands (bits stored as unsigned)
__device__ __align__(16) unsigned g_xt [MTOT*EMBED];
__device__ __align__(16) unsigned g_Wqt[EMBED*EMBED];
__device__ __align__(16) unsigned g_Wkt[EMBED*EMBED];
__device__ __align__(16) unsigned g_Wvt[EMBED*EMBED];
__device__ __align__(16) unsigned g_Wot[EMBED*EMBED];

// ---------------------------------------------------------------------------
// helpers
// ---------------------------------------------------------------------------
__device__ __forceinline__ unsigned f2tf(float f) {
    unsigned u;
    asm("cvt.rna.tf32.f32 %0, %1;" : "=r"(u) : "f"(f));
    return u;
}
__device__ __forceinline__ float tf32r(float f) { return __uint_as_float(f2tf(f)); }

// D += A*B   (m16n8k8 tf32, row.col)
__device__ __forceinline__ void mma8(float* d, const unsigned* a, const unsigned* b) {
    asm volatile(
        "mma.sync.aligned.m16n8k8.row.col.f32.tf32.tf32.f32 "
        "{%0,%1,%2,%3}, {%4,%5,%6,%7}, {%8,%9}, {%0,%1,%2,%3};"
        : "+f"(d[0]), "+f"(d[1]), "+f"(d[2]), "+f"(d[3])
        : "r"(a[0]), "r"(a[1]), "r"(a[2]), "r"(a[3]), "r"(b[0]), "r"(b[1]));
}

__device__ __forceinline__ void cpa16(unsigned saddr, const void* g) {
    asm volatile("cp.async.cg.shared.global [%0], [%1], 16;" :: "r"(saddr), "l"(g));
}
__device__ __forceinline__ void cpa_commit() {
    asm volatile("cp.async.commit_group;" ::: "memory");
}

// ---------------------------------------------------------------------------
// Pre-conversion: fp32 -> tf32 bits (vectorized)
// ---------------------------------------------------------------------------
__global__ void conv_tf32(const float* __restrict__ s, unsigned* __restrict__ d, int n4) {
    int i = blockIdx.x*blockDim.x + threadIdx.x;
    if (i < n4) {
        float4 v = ((const float4*)s)[i];
        ((uint4*)d)[i] = make_uint4(f2tf(v.x), f2tf(v.y), f2tf(v.z), f2tf(v.w));
    }
}

// ---------------------------------------------------------------------------
// TF32 GEMM, cp.async double-buffered.
// CTA tile 256(M) x 128(N), ktile 32. 8 warps, each 64x64.
// smem row-major [row][KP=36] per operand (conflict-free fragment LDS).
// ---------------------------------------------------------------------------
#define KP    36
#define ASTW  (256*KP)          // 9216 words
#define BSTW  (128*KP)          // 4608 words
#define STGW  (ASTW+BSTW)       // words per stage

__device__ __forceinline__ void issue_rows(unsigned* Sm, const unsigned* __restrict__ src,
                                           int row0, int k0, int tid, int nchunks8) {
    // nchunks8: iterations of 256 threads; each thread copies one 16B chunk
    #pragma unroll
    for (int it = 0; it < 8; it++) {
        if (it >= nchunks8) break;
        int lin = tid + 256*it;
        int rr = lin >> 3, ch = lin & 7;
        unsigned sa = (unsigned)__cvta_generic_to_shared(&Sm[rr*KP + ch*4]);
        cpa16(sa, &src[(size_t)(row0+rr)*EMBED + k0 + ch*4]);
    }
}

__device__ __forceinline__ void compute_stage(const unsigned* __restrict__ As,
                                              const unsigned* __restrict__ Bs,
                                              float acc[4][8][4],
                                              int wm, int wn, int g, int s) {
    #pragma unroll
    for (int kt = 0; kt < 4; kt++) {
        const int kc = kt*8 + s;
        unsigned a[4][4], b[8][2];
        #pragma unroll
        for (int i = 0; i < 4; i++) {
            const unsigned* p = &As[(wm + 16*i + g)*KP + kc];
            a[i][0] = p[0];
            a[i][1] = p[8*KP];
            a[i][2] = p[4];
            a[i][3] = p[8*KP + 4];
        }
        #pragma unroll
        for (int j = 0; j < 8; j++) {
            const unsigned* p = &Bs[(wn + 8*j + g)*KP + kc];
            b[j][0] = p[0];
            b[j][1] = p[4];
        }
        #pragma unroll
        for (int i = 0; i < 4; i++)
            #pragma unroll
            for (int j = 0; j < 8; j++)
                mma8(acc[i][j], a[i], b[j]);
    }
}

__global__ __launch_bounds__(256) void qkv_gemm_tc(
    const float* __restrict__ bq, const float* __restrict__ bk, const float* __restrict__ bv)
{
    const int p = blockIdx.z;
    const unsigned* __restrict__ Wt = (p==0) ? g_Wqt : (p==1 ? g_Wkt : g_Wvt);
    const float*    __restrict__ bias = (p==0) ? bq : (p==1 ? bk : bv);
    float*          __restrict__ outp = (p==0) ? g_Q : (p==1 ? g_K : g_V);

    extern __shared__ unsigned smg[];

    const int tid  = threadIdx.x;
    const int w    = tid >> 5;
    const int lane = tid & 31;
    const int g    = lane >> 2;
    const int s    = lane & 3;
    const int wm   = (w & 3) * 64;      // 4 warps along M
    const int wn   = (w >> 2) * 64;     // 2 warps along N
    const int m0   = blockIdx.y * 256;
    const int n0   = blockIdx.x * 128;

    float acc[4][8][4];
    #pragma unroll
    for (int i = 0; i < 4; i++)
        #pragma unroll
        for (int j = 0; j < 8; j++)
            #pragma unroll
            for (int c = 0; c < 4; c++) acc[i][j][c] = 0.f;

    // prologue: stage 0
    issue_rows(smg,        g_xt, m0, 0, tid, 8);
    issue_rows(smg + ASTW, Wt,   n0, 0, tid, 4);
    cpa_commit();

    int buf = 0;
    for (int k0 = 0; k0 < EMBED; k0 += 32) {
        const bool more = (k0 + 32) < EMBED;
        if (more) {
            unsigned* st = smg + (buf^1)*STGW;
            issue_rows(st,        g_xt, m0, k0+32, tid, 8);
            issue_rows(st + ASTW, Wt,   n0, k0+32, tid, 4);
            cpa_commit();
            asm volatile("cp.async.wait_group 1;" ::: "memory");
        } else {
            asm volatile("cp.async.wait_group 0;" ::: "memory");
        }
        __syncthreads();
        const unsigned* st = smg + buf*STGW;
        compute_stage(st, st + ASTW, acc, wm, wn, g, s);
        __syncthreads();
        buf ^= 1;
    }

    // Epilogue: scatter to [b][h][n][d], tf32-rounded + bias
    #pragma unroll
    for (int i = 0; i < 4; i++) {
        const int m  = m0 + wm + 16*i + g;
        const int b_ = m >> 10;
        const int nn = m & 1023;
        #pragma unroll
        for (int j = 0; j < 8; j++) {
            const int c  = n0 + wn + 8*j + 2*s;
            const int h  = c >> 6;
            const int d  = c & 63;
            const float b0v = bias[c], b1v = bias[c+1];
            float2 v0 = make_float2(tf32r(acc[i][j][0] + b0v), tf32r(acc[i][j][1] + b1v));
            float2 v1 = make_float2(tf32r(acc[i][j][2] + b0v), tf32r(acc[i][j][3] + b1v));
            *(float2*)&outp[(((size_t)b_*NHEADS + h)*SEQ + nn    )*HDIM + d] = v0;
            *(float2*)&outp[(((size_t)b_*NHEADS + h)*SEQ + nn + 8)*HDIM + d] = v1;
        }
    }
}

__device__ __forceinline__ void issue_rowsA_gather(unsigned* Sm, int m0, int k0, int tid) {
    #pragma unroll
    for (int it = 0; it < 8; it++) {
        int lin = tid + 256*it;
        int rr = lin >> 3, ch = lin & 7;
        const int m  = m0 + rr;
        const int b_ = m >> 10;
        const int nn = m & 1023;
        const int k  = k0 + ch*4;
        const int h  = k >> 6;
        const int d  = k & 63;
        unsigned sa = (unsigned)__cvta_generic_to_shared(&Sm[rr*KP + ch*4]);
        cpa16(sa, &g_A[(((size_t)b_*NHEADS + h)*SEQ + nn)*HDIM + d]);
    }
}

__global__ __launch_bounds__(256) void out_gemm_tc(
    const float* __restrict__ bo, float* __restrict__ out)
{
    extern __shared__ unsigned smg[];

    const int tid  = threadIdx.x;
    const int w    = tid >> 5;
    const int lane = tid & 31;
    const int g    = lane >> 2;
    const int s    = lane & 3;
    const int wm   = (w & 3) * 64;
    const int wn   = (w >> 2) * 64;
    const int m0   = blockIdx.y * 256;
    const int n0   = blockIdx.x * 128;

    float acc[4][8][4];
    #pragma unroll
    for (int i = 0; i < 4; i++)
        #pragma unroll
        for (int j = 0; j < 8; j++)
            #pragma unroll
            for (int c = 0; c < 4; c++) acc[i][j][c] = 0.f;

    issue_rowsA_gather(smg, m0, 0, tid);
    issue_rows(smg + ASTW, g_Wot, n0, 0, tid, 4);
    cpa_commit();

    int buf = 0;
    for (int k0 = 0; k0 < EMBED; k0 += 32) {
        const bool more = (k0 + 32) < EMBED;
        if (more) {
            unsigned* st = smg + (buf^1)*STGW;
            issue_rowsA_gather(st, m0, k0+32, tid);
            issue_rows(st + ASTW, g_Wot, n0, k0+32, tid, 4);
            cpa_commit();
            asm volatile("cp.async.wait_group 1;" ::: "memory");
        } else {
            asm volatile("cp.async.wait_group 0;" ::: "memory");
        }
        __syncthreads();
        const unsigned* st = smg + buf*STGW;
        compute_stage(st, st + ASTW, acc, wm, wn, g, s);
        __syncthreads();
        buf ^= 1;
    }

    // Epilogue: row-major fp32 out + bias (full precision)
    #pragma unroll
    for (int i = 0; i < 4; i++) {
        const int m = m0 + wm + 16*i + g;
        #pragma unroll
        for (int j = 0; j < 8; j++) {
            const int c = n0 + wn + 8*j + 2*s;
            const float b0v = bo[c], b1v = bo[c+1];
            float2 v0 = make_float2(acc[i][j][0] + b0v, acc[i][j][1] + b1v);
            float2 v1 = make_float2(acc[i][j][2] + b0v, acc[i][j][3] + b1v);
            *(float2*)&out[(size_t)m*EMBED + c]     = v0;
            *(float2*)&out[(size_t)(m+8)*EMBED + c] = v1;
        }
    }
}

// ---------------------------------------------------------------------------
// Flash attention, tensor cores, double-buffered K/V with register prefetch.
// Inputs are tf32-valued fp32 -> fills store raw bits (no cvt in loop).
// Br=128 q-rows/CTA, Bc=64 keys/tile, 256 threads / 8 warps.
// smem: sQ [64][136] (reused as sP [128][72]) | sK[2][64][72] | sV[2][64][72]
// ---------------------------------------------------------------------------
#define KSTR  136
#define PSTR  72
#define KVW   (64*PSTR)

__global__ __launch_bounds__(256) void attn_tc()
{
    extern __shared__ unsigned smu[];
    unsigned* sQ = smu;                    // [d=64][m+pad=136]
    unsigned* sP = smu;                    // [m=128][key+pad=72]
    unsigned* sK = smu + 9216;             // 2 buffers [d][key+pad]
    unsigned* sV = sK + 2*KVW;             // 2 buffers [key][d+pad]

    const int tid  = threadIdx.x;
    const int w    = tid >> 5;
    const int lane = tid & 31;
    const int g    = lane >> 2;
    const int s    = lane & 3;
    const int bh   = blockIdx.y;
    const int q0   = blockIdx.x * 128;
    const int r0   = 16*w + g;
    const int r1   = r0 + 8;

    const float* __restrict__ Qg = g_Q + ((size_t)bh*SEQ + q0)*HDIM;
    const float* __restrict__ Kg = g_K + (size_t)bh*SEQ*HDIM;
    const float* __restrict__ Vg = g_V + (size_t)bh*SEQ*HDIM;
    float* __restrict__ Og = g_A + ((size_t)bh*SEQ + q0)*HDIM;

    float4 kreg[4], vreg[4];

    // prefetch KV tile 0
    #pragma unroll
    for (int it = 0; it < 4; it++) {
        int lin = tid + 256*it;
        int rr = lin >> 4, dq = lin & 15;
        kreg[it] = *(const float4*)&Kg[(size_t)rr*HDIM + dq*4];
        vreg[it] = *(const float4*)&Vg[(size_t)rr*HDIM + dq*4];
    }

    // ---- load Q (128 x 64), transpose to [d][m], scale (exact pow2) ----
    #pragma unroll
    for (int it = 0; it < 8; it++) {
        int lin = tid + 256*it;
        int rr = lin >> 4;
        int dq = lin & 15;
        const float4 q = *(const float4*)&Qg[rr*HDIM + dq*4];
        float qq[4] = {q.x*ATT_SCALE, q.y*ATT_SCALE, q.z*ATT_SCALE, q.w*ATT_SCALE};
        #pragma unroll
        for (int c = 0; c < 4; c++) {
            int cc = (c + dq) & 3;
            sQ[(dq*4 + cc)*KSTR + rr] = __float_as_uint(qq[cc]);
        }
    }

    // store KV tile 0 into buffer 0 (raw bits; already tf32-valued)
    #pragma unroll
    for (int it = 0; it < 4; it++) {
        int lin = tid + 256*it;
        int rr = lin >> 4, dq = lin & 15;
        float kk4[4] = {kreg[it].x, kreg[it].y, kreg[it].z, kreg[it].w};
        #pragma unroll
        for (int c = 0; c < 4; c++) {
            int cc = (c + dq) & 3;
            sK[(dq*4 + cc)*PSTR + rr] = __float_as_uint(kk4[cc]);
        }
        *(uint4*)&sV[rr*PSTR + dq*4] = make_uint4(
            __float_as_uint(vreg[it].x), __float_as_uint(vreg[it].y),
            __float_as_uint(vreg[it].z), __float_as_uint(vreg[it].w));
    }
    __syncthreads();

    // cache Q A-fragments in registers
    unsigned qa[8][4];
    #pragma unroll
    for (int kt = 0; kt < 8; kt++) {
        const int base = (8*kt + s)*KSTR + 16*w + g;
        qa[kt][0] = sQ[base];
        qa[kt][1] = sQ[base + 8];
        qa[kt][2] = sQ[base + 4*KSTR];
        qa[kt][3] = sQ[base + 4*KSTR + 8];
    }

    float o[8][4];
    #pragma unroll
    for (int j = 0; j < 8; j++)
        #pragma unroll
        for (int c = 0; c < 4; c++) o[j][c] = 0.f;
    float mr0 = -1e30f, mr1 = -1e30f, lr0 = 0.f, lr1 = 0.f;

    int buf = 0;
    for (int t = 0; t < SEQ/64; t++) {
        const bool more = (t + 1) < SEQ/64;
        if (more) {
            #pragma unroll
            for (int it = 0; it < 4; it++) {
                int lin = tid + 256*it;
                int rr = lin >> 4, dq = lin & 15;
                kreg[it] = *(const float4*)&Kg[(size_t)((t+1)*64 + rr)*HDIM + dq*4];
                vreg[it] = *(const float4*)&Vg[(size_t)((t+1)*64 + rr)*HDIM + dq*4];
            }
        }

        const unsigned* sKb = sK + buf*KVW;
        const unsigned* sVb = sV + buf*KVW;

        // ---- S = Q @ K^T (128x64) ----
        float sc[8][4];
        #pragma unroll
        for (int j = 0; j < 8; j++)
            #pragma unroll
            for (int c = 0; c < 4; c++) sc[j][c] = 0.f;
        #pragma unroll
        for (int kt = 0; kt < 8; kt++) {
            unsigned kb[8][2];
            #pragma unroll
            for (int j = 0; j < 8; j++) {
                const int base = (8*kt + s)*PSTR + 8*j + g;
                kb[j][0] = sKb[base];
                kb[j][1] = sKb[base + 4*PSTR];
            }
            #pragma unroll
            for (int j = 0; j < 8; j++)
                mma8(sc[j], qa[kt], kb[j]);
        }

        // ---- online softmax ----
        float mx0 = -1e30f, mx1 = -1e30f;
        #pragma unroll
        for (int j = 0; j < 8; j++) {
            mx0 = fmaxf(mx0, fmaxf(sc[j][0], sc[j][1]));
            mx1 = fmaxf(mx1, fmaxf(sc[j][2], sc[j][3]));
        }
        mx0 = fmaxf(mx0, __shfl_xor_sync(0xffffffffu, mx0, 1));
        mx0 = fmaxf(mx0, __shfl_xor_sync(0xffffffffu, mx0, 2));
        mx1 = fmaxf(mx1, __shfl_xor_sync(0xffffffffu, mx1, 1));
        mx1 = fmaxf(mx1, __shfl_xor_sync(0xffffffffu, mx1, 2));
        const float mn0 = fmaxf(mr0, mx0);
        const float mn1 = fmaxf(mr1, mx1);
        const float al0 = __expf(mr0 - mn0);
        const float al1 = __expf(mr1 - mn1);
        mr0 = mn0; mr1 = mn1;
        float sum0 = 0.f, sum1 = 0.f;
        #pragma unroll
        for (int j = 0; j < 8; j++) {
            sc[j][0] = __expf(sc[j][0] - mn0);
            sc[j][1] = __expf(sc[j][1] - mn0);
            sc[j][2] = __expf(sc[j][2] - mn1);
            sc[j][3] = __expf(sc[j][3] - mn1);
            sum0 += sc[j][0] + sc[j][1];
            sum1 += sc[j][2] + sc[j][3];
        }
        sum0 += __shfl_xor_sync(0xffffffffu, sum0, 1);
        sum0 += __shfl_xor_sync(0xffffffffu, sum0, 2);
        sum1 += __shfl_xor_sync(0xffffffffu, sum1, 1);
        sum1 += __shfl_xor_sync(0xffffffffu, sum1, 2);
        lr0 = lr0*al0 + sum0;
        lr1 = lr1*al1 + sum1;
        #pragma unroll
        for (int j = 0; j < 8; j++) {
            o[j][0] *= al0; o[j][1] *= al0;
            o[j][2] *= al1; o[j][3] *= al1;
        }

        __syncthreads();   // prev PV readers of sP and buf^1 done

        // ---- store P (tf32) + stage next KV into other buffer ----
        #pragma unroll
        for (int j = 0; j < 8; j++) {
            *(uint2*)&sP[r0*PSTR + 8*j + 2*s] = make_uint2(f2tf(sc[j][0]), f2tf(sc[j][1]));
            *(uint2*)&sP[r1*PSTR + 8*j + 2*s] = make_uint2(f2tf(sc[j][2]), f2tf(sc[j][3]));
        }
        if (more) {
            unsigned* sKn = sK + (buf^1)*KVW;
            unsigned* sVn = sV + (buf^1)*KVW;
            #pragma unroll
            for (int it = 0; it < 4; it++) {
                int lin = tid + 256*it;
                int rr = lin >> 4, dq = lin & 15;
                float kk4[4] = {kreg[it].x, kreg[it].y, kreg[it].z, kreg[it].w};
                #pragma unroll
                for (int c = 0; c < 4; c++) {
                    int cc = (c + dq) & 3;
                    sKn[(dq*4 + cc)*PSTR + rr] = __float_as_uint(kk4[cc]);
                }
                *(uint4*)&sVn[rr*PSTR + dq*4] = make_uint4(
                    __float_as_uint(vreg[it].x), __float_as_uint(vreg[it].y),
                    __float_as_uint(vreg[it].z), __float_as_uint(vreg[it].w));
            }
        }
        __syncthreads();

        // ---- O += P @ V ----
        #pragma unroll
        for (int kt = 0; kt < 8; kt++) {
            unsigned pa[4];
            pa[0] = sP[r0*PSTR + 8*kt + s];
            pa[1] = sP[r1*PSTR + 8*kt + s];
            pa[2] = sP[r0*PSTR + 8*kt + s + 4];
            pa[3] = sP[r1*PSTR + 8*kt + s + 4];
            #pragma unroll
            for (int j = 0; j < 8; j++) {
                unsigned vb[2];
                const int base = (8*kt + s)*PSTR + 8*j + g;
                vb[0] = sVb[base];
                vb[1] = sVb[base + 4*PSTR];
                mma8(o[j], pa, vb);
            }
        }
        buf ^= 1;
    }

    // ---- normalize + store (tf32-rounded for out_gemm consumption) ----
    const float il0 = 1.f / lr0;
    const float il1 = 1.f / lr1;
    #pragma unroll
    for (int j = 0; j < 8; j++) {
        *(float2*)&Og[r0*HDIM + 8*j + 2*s] =
            make_float2(tf32r(o[j][0]*il0), tf32r(o[j][1]*il0));
        *(float2*)&Og[r1*HDIM + 8*j + 2*s] =
            make_float2(tf32r(o[j][2]*il1), tf32r(o[j][3]*il1));
    }
}

// ---------------------------------------------------------------------------
extern "C" void kernel_launch(void* const* d_in, const int* in_sizes, int n_in,
                              void* d_out, int out_size)
{
    const float* x  = (const float*)d_in[0];
    const float* Wq = (const float*)d_in[1];
    const float* bq = (const float*)d_in[2];
    const float* Wk = (const float*)d_in[3];
    const float* bk = (const float*)d_in[4];
    const float* Wv = (const float*)d_in[5];
    const float* bv = (const float*)d_in[6];
    const float* Wo = (const float*)d_in[7];
    const float* bo = (const float*)d_in[8];
    float* out = (float*)d_out;

    // resolve device-global addresses
    unsigned *xt_p, *wq_p, *wk_p, *wv_p, *wo_p;
    cudaGetSymbolAddress((void**)&xt_p, g_xt);
    cudaGetSymbolAddress((void**)&wq_p, g_Wqt);
    cudaGetSymbolAddress((void**)&wk_p, g_Wkt);
    cudaGetSymbolAddress((void**)&wv_p, g_Wvt);
    cudaGetSymbolAddress((void**)&wo_p, g_Wot);

    // pre-convert operands to tf32
    const int NX4 = MTOT*EMBED/4, NW4 = EMBED*EMBED/4;
    conv_tf32<<<(NX4+255)/256, 256>>>(x,  xt_p, NX4);
    conv_tf32<<<(NW4+255)/256, 256>>>(Wq, wq_p, NW4);
    conv_tf32<<<(NW4+255)/256, 256>>>(Wk, wk_p, NW4);
    conv_tf32<<<(NW4+255)/256, 256>>>(Wv, wv_p, NW4);
    conv_tf32<<<(NW4+255)/256, 256>>>(Wo, wo_p, NW4);

    const int smem_gemm = 2*STGW*(int)sizeof(unsigned);              // 110592 B
    const int smem_attn = (9216 + 4*KVW)*(int)sizeof(unsigned);      // 110592 B

    cudaFuncSetAttribute(qkv_gemm_tc, cudaFuncAttributeMaxDynamicSharedMemorySize, smem_gemm);
    cudaFuncSetAttribute(out_gemm_tc, cudaFuncAttributeMaxDynamicSharedMemorySize, smem_gemm);
    cudaFuncSetAttribute(attn_tc,     cudaFuncAttributeMaxDynamicSharedMemorySize, smem_attn);

    // QKV projections
    dim3 g1(EMBED/128, MTOT/256, 3);
    qkv_gemm_tc<<<g1, 256, smem_gemm>>>(bq, bk, bv);

    // Flash attention
    dim3 g2(SEQ/128, BHEADS);
    attn_tc<<<g2, 256, smem_attn>>>();

    // Output projection
    dim3 g3(EMBED/128, MTOT/256);
    out_gemm_tc<<<g3, 256, smem_gemm>>>(bo, out);
}